// round 16
// baseline (speedup 1.0000x reference)
#include <cuda_runtime.h>

// TemperatureScaler: piecewise-linear temperature scaling of logits.
// out = T[b]*x + C[b],  b = searchsorted(sorted_thr, x, 'left').
// L2 policy steering via createpolicy + L2::cache_hint (valid PTX form):
// input loads pinned evict_last, output stores streamed with st.global.cs.

#define TS_TEMP_MIN 1e-4f
#define TS_MAGIC    12582912.0f   // 2^23 + 2^22: fp add rounds to int in mantissa

// 128-bit load, non-coherent, with evict_last cache-policy descriptor
#define TS_LD128_EL(p, pol, x0, x1, x2, x3)                                    \
    asm volatile("ld.global.nc.L2::cache_hint.v4.f32 {%0,%1,%2,%3}, [%4], %5;" \
        : "=f"(x0), "=f"(x1), "=f"(x2), "=f"(x3) : "l"(p), "l"(pol))

// 128-bit streaming store (evict-first, minimal L2 pollution)
#define TS_ST128_CS(p, x0, x1, x2, x3)                                         \
    asm volatile("st.global.cs.v4.f32 [%0], {%1,%2,%3,%4};"                    \
        :: "l"(p), "f"(x0), "f"(x1), "f"(x2), "f"(x3) : "memory")

__device__ __forceinline__ unsigned long long ts_policy_evict_last() {
    unsigned long long pol;
    asm("createpolicy.fractional.L2::evict_last.b64 %0, 1.0;" : "=l"(pol));
    return pol;
}

__device__ __forceinline__ void ts_build_params(
    const float* __restrict__ temperature, const float* __restrict__ thresholds,
    float* th /*7 sorted*/, float* T /*8*/, float* C /*8*/)
{
    #pragma unroll
    for (int i = 0; i < 7; i++) th[i] = thresholds[i];
    // insertion sort (7 elements) == jnp.sort
    #pragma unroll
    for (int i = 1; i < 7; i++) {
        float v = th[i];
        int j = i - 1;
        while (j >= 0 && th[j] > v) { th[j + 1] = th[j]; j--; }
        th[j + 1] = v;
    }
    #pragma unroll
    for (int i = 0; i < 8; i++) {
        float t = temperature[i];
        T[i] = t < TS_TEMP_MIN ? TS_TEMP_MIN : t;   // clip(lo=1e-4)
    }
    float thrp[8];
    thrp[0] = 0.0f;
    #pragma unroll
    for (int i = 0; i < 7; i++) thrp[i + 1] = th[i];
    // c = cumsum(diff(pad(thr, left0)) * T[:-1])
    float c[8];
    c[0] = 0.0f;
    #pragma unroll
    for (int i = 0; i < 7; i++) {
        float d = __fadd_rn(thrp[i + 1], -thrp[i]);
        c[i + 1] = __fadd_rn(c[i], __fmul_rn(d, T[i]));
    }
    // C[b] = c[b] - T[b]*thrp[b]  (single-FFMA form; ulp-level deviation only)
    #pragma unroll
    for (int i = 0; i < 8; i++) C[i] = __fmaf_rn(-T[i], thrp[i], c[i]);
}

__global__ __launch_bounds__(256, 7) void ts_kernel(
    const float* __restrict__ in, float* __restrict__ out,
    const float* __restrict__ temperature, const float* __restrict__ thresholds,
    int n4)
{
    __shared__ float2 lut[8];   // (T, C)
    __shared__ float sthr[7];   // sorted thresholds (fallback)
    __shared__ float s_inv, s_f;
    __shared__ int   s_uniform;

    if (threadIdx.x == 0) {
        float th[7], T[8], C[8];
        ts_build_params(temperature, thresholds, th, T, C);
        #pragma unroll
        for (int i = 0; i < 8; i++) lut[i] = make_float2(T[i], C[i]);
        #pragma unroll
        for (int i = 0; i < 7; i++) sthr[i] = th[i];

        // near-uniform grid detection: th[i] ~ th0 + i*s with s = span/6
        float span = __fadd_rn(th[6], -th[0]);
        float s    = __fmul_rn(span, 1.0f / 6.0f);
        int uni = (s > 0.0f);
        float tol = 1e-5f * (fabsf(span) + 1.0f);
        #pragma unroll
        for (int i = 0; i < 7; i++) {
            float ideal = __fmaf_rn((float)i, s, th[0]);
            if (fabsf(th[i] - ideal) > tol) uni = 0;
        }
        float inv = uni ? (1.0f / s) : 0.0f;
        s_inv = inv;
        s_f   = __fmaf_rn(-th[0], inv, 0.5f);
        s_uniform = uni;
    }
    __syncthreads();

    const unsigned long long pol = ts_policy_evict_last();
    const int base = blockIdx.x * 2048 + threadIdx.x;   // float4 index

    if (s_uniform) {
        const float inv = s_inv, f = s_f;
        auto piece = [&](float x) -> float {
            float y1 = __fmaf_rn(x, inv, f);          // (x-a)/s + 0.5
            y1 = fmaxf(y1, 0.0f);                     // clamp low (NaN -> 0)
            y1 = fminf(y1, 7.0f);                     // clamp high
            float y  = __fadd_rn(y1, TS_MAGIC);       // round-to-nearest int
            int b = __float_as_int(y) & 7;            // bin
            float2 L = lut[b];                        // LDS.64, conflict-free
            return __fmaf_rn(L.x, x, L.y);
        };
        if (base + 1792 < n4) {
            // two halves, each: 4 independent LDG.128 (evict_last policy),
            // then compute + streaming stores
            #pragma unroll
            for (int half = 0; half < 2; half++) {
                const int o = base + half * 1024;
                float a0,a1,a2,a3, b0,b1,b2,b3, c0,c1,c2,c3, d0,d1,d2,d3;
                TS_LD128_EL(in + 4LL*o,         pol, a0,a1,a2,a3);
                TS_LD128_EL(in + 4LL*(o + 256), pol, b0,b1,b2,b3);
                TS_LD128_EL(in + 4LL*(o + 512), pol, c0,c1,c2,c3);
                TS_LD128_EL(in + 4LL*(o + 768), pol, d0,d1,d2,d3);
                a0 = piece(a0); a1 = piece(a1); a2 = piece(a2); a3 = piece(a3);
                b0 = piece(b0); b1 = piece(b1); b2 = piece(b2); b3 = piece(b3);
                c0 = piece(c0); c1 = piece(c1); c2 = piece(c2); c3 = piece(c3);
                d0 = piece(d0); d1 = piece(d1); d2 = piece(d2); d3 = piece(d3);
                TS_ST128_CS(out + 4LL*o,         a0,a1,a2,a3);
                TS_ST128_CS(out + 4LL*(o + 256), b0,b1,b2,b3);
                TS_ST128_CS(out + 4LL*(o + 512), c0,c1,c2,c3);
                TS_ST128_CS(out + 4LL*(o + 768), d0,d1,d2,d3);
            }
        } else {
            #pragma unroll
            for (int k = 0; k < 8; k++) {
                int i = base + k * 256;
                if (i < n4) {
                    float a0,a1,a2,a3;
                    TS_LD128_EL(in + 4LL*i, pol, a0,a1,a2,a3);
                    a0 = piece(a0); a1 = piece(a1); a2 = piece(a2); a3 = piece(a3);
                    TS_ST128_CS(out + 4LL*i, a0,a1,a2,a3);
                }
            }
        }
    } else {
        // generic fallback: compare-chain bin search
        const float t0 = sthr[0], t1 = sthr[1], t2 = sthr[2], t3 = sthr[3],
                    t4 = sthr[4], t5 = sthr[5], t6 = sthr[6];
        auto piece = [&](float x) -> float {
            int b = (x > t0);
            b += (x > t1); b += (x > t2); b += (x > t3);
            b += (x > t4); b += (x > t5); b += (x > t6);
            float2 L = lut[b];
            return __fmaf_rn(L.x, x, L.y);
        };
        #pragma unroll
        for (int k = 0; k < 8; k++) {
            int i = base + k * 256;
            if (i < n4) {
                float a0,a1,a2,a3;
                TS_LD128_EL(in + 4LL*i, pol, a0,a1,a2,a3);
                a0 = piece(a0); a1 = piece(a1); a2 = piece(a2); a3 = piece(a3);
                TS_ST128_CS(out + 4LL*i, a0,a1,a2,a3);
            }
        }
    }
}

// Scalar tail for out_size % 4 != 0 (not hit for B=64, V=128000)
__global__ void ts_tail_kernel(
    const float* __restrict__ in, float* __restrict__ out,
    const float* __restrict__ temperature, const float* __restrict__ thresholds,
    int start, int n)
{
    float th[7], T[8], C[8];
    ts_build_params(temperature, thresholds, th, T, C);
    for (int i = start + threadIdx.x; i < n; i += blockDim.x) {
        float x = in[i];
        int b = 0;
        #pragma unroll
        for (int j = 0; j < 7; j++) b += (x > th[j]);
        out[i] = __fmaf_rn(T[b], x, C[b]);
    }
}

extern "C" void kernel_launch(void* const* d_in, const int* in_sizes, int n_in,
                              void* d_out, int out_size) {
    const float* logits      = (const float*)d_in[0];
    const float* temperature = (const float*)d_in[1];
    const float* thresholds  = (const float*)d_in[2];
    float* out = (float*)d_out;

    int n  = out_size;           // 8,192,000
    int n4 = n >> 2;             // 2,048,000 float4s

    int grid = (n4 + 2047) / 2048;   // 8 float4 per thread -> 1000 blocks
    if (grid < 1) grid = 1;

    ts_kernel<<<grid, 256>>>(logits, out, temperature, thresholds, n4);

    int rem = n - (n4 << 2);
    if (rem > 0) {
        ts_tail_kernel<<<1, 256>>>(logits, out, temperature, thresholds, n4 << 2, n);
    }
}